// round 1
// baseline (speedup 1.0000x reference)
#include <cuda_runtime.h>

#define BATCH 8
#define SEQ   2048
#define DIM   512
#define DKK   64

// Scratch (module-load allocated, legal under _HX_ENFORCE)
__device__ float g_Q[BATCH * SEQ * DKK];
__device__ float g_K[BATCH * SEQ * DKK];
__device__ float g_V[BATCH * SEQ * DKK];

// ---------------------------------------------------------------------------
// Kernel 1: QKV projection. One block per (b,s) row. 192 threads:
// threads [0,64) -> Q, [64,128) -> K, [128,192) -> V.
// ---------------------------------------------------------------------------
__global__ void qkv_kernel(const float* __restrict__ in,
                           const float* __restrict__ Wq,
                           const float* __restrict__ Wk,
                           const float* __restrict__ Wv) {
    __shared__ float sh[DIM];
    const int row = blockIdx.x;                 // 0 .. BATCH*SEQ-1
    const float* inrow = in + (size_t)row * DIM;

    for (int d = threadIdx.x; d < DIM; d += blockDim.x)
        sh[d] = inrow[d];
    __syncthreads();

    const int t     = threadIdx.x;              // 0..191
    const int which = t / DKK;                  // 0,1,2
    const int k     = t % DKK;
    const float* W  = (which == 0) ? Wq : (which == 1) ? Wk : Wv;

    float acc = 0.f;
#pragma unroll 8
    for (int d = 0; d < DIM; d++)
        acc += sh[d] * W[d * DKK + k];

    float* out = (which == 0) ? g_Q : (which == 1) ? g_K : g_V;
    out[(size_t)row * DKK + k] = acc;
}

// ---------------------------------------------------------------------------
// Kernel 2: scores = scale * Q @ K^T  per batch.  64x64 block tile, DK=64 full
// reduction in shared memory. 256 threads, 4x4 micro-tile per thread.
// Writes directly into the weights region of d_out.
// ---------------------------------------------------------------------------
__global__ void scores_kernel(float* __restrict__ weights) {
    __shared__ float Qs[64][DKK + 1];
    __shared__ float Ks[64][DKK + 1];

    const int b  = blockIdx.z;
    const int m0 = blockIdx.y * 64;
    const int n0 = blockIdx.x * 64;
    const float* Qb = g_Q + (size_t)b * SEQ * DKK;
    const float* Kb = g_K + (size_t)b * SEQ * DKK;

    const int tid = threadIdx.x;
    for (int i = tid; i < 64 * DKK; i += 256) {
        const int r = i / DKK, c = i % DKK;
        Qs[r][c] = Qb[(size_t)(m0 + r) * DKK + c];
        Ks[r][c] = Kb[(size_t)(n0 + r) * DKK + c];
    }
    __syncthreads();

    const int tx = tid % 16;   // 16 n-positions * 4
    const int ty = tid / 16;   // 16 m-positions * 4

    float acc[4][4] = {};
#pragma unroll
    for (int k = 0; k < DKK; k++) {
        float qr[4], kr[4];
#pragma unroll
        for (int i = 0; i < 4; i++) qr[i] = Qs[ty * 4 + i][k];
#pragma unroll
        for (int j = 0; j < 4; j++) kr[j] = Ks[tx * 4 + j][k];
#pragma unroll
        for (int i = 0; i < 4; i++)
#pragma unroll
            for (int j = 0; j < 4; j++)
                acc[i][j] += qr[i] * kr[j];
    }

    const float scale = 0.125f;  // 1/sqrt(64)
    float* outb = weights + (size_t)b * SEQ * SEQ;
#pragma unroll
    for (int i = 0; i < 4; i++) {
        const int row = m0 + ty * 4 + i;
        float4 v;
        v.x = acc[i][0] * scale;
        v.y = acc[i][1] * scale;
        v.z = acc[i][2] * scale;
        v.w = acc[i][3] * scale;
        *reinterpret_cast<float4*>(outb + (size_t)row * SEQ + n0 + tx * 4) = v;
    }
}

// ---------------------------------------------------------------------------
// Kernel 3: row softmax over S=2048, in place in the weights region.
// One block (256 threads) per row, 8 elements per thread in registers.
// ---------------------------------------------------------------------------
__global__ void softmax_kernel(float* __restrict__ weights) {
    const int row = blockIdx.x;                 // 0 .. BATCH*SEQ-1
    float* w = weights + (size_t)row * SEQ;
    const int tid  = threadIdx.x;
    const int lane = tid & 31;
    const int warp = tid >> 5;

    float v[8];
    float mx = -3.4e38f;
#pragma unroll
    for (int i = 0; i < 8; i++) {
        v[i] = w[tid + i * 256];
        mx = fmaxf(mx, v[i]);
    }
#pragma unroll
    for (int o = 16; o > 0; o >>= 1)
        mx = fmaxf(mx, __shfl_xor_sync(0xffffffffu, mx, o));

    __shared__ float redmax[8];
    __shared__ float redsum[8];
    if (lane == 0) redmax[warp] = mx;
    __syncthreads();
    float bm = redmax[0];
#pragma unroll
    for (int i = 1; i < 8; i++) bm = fmaxf(bm, redmax[i]);

    float s = 0.f;
#pragma unroll
    for (int i = 0; i < 8; i++) {
        v[i] = __expf(v[i] - bm);
        s += v[i];
    }
#pragma unroll
    for (int o = 16; o > 0; o >>= 1)
        s += __shfl_xor_sync(0xffffffffu, s, o);
    if (lane == 0) redsum[warp] = s;
    __syncthreads();
    float total = 0.f;
#pragma unroll
    for (int i = 0; i < 8; i++) total += redsum[i];
    const float inv = 1.0f / total;

#pragma unroll
    for (int i = 0; i < 8; i++)
        w[tid + i * 256] = v[i] * inv;
}

// ---------------------------------------------------------------------------
// Kernel 4: attended = weights @ V  per batch.  Block computes a 64x64 output
// tile (64 q-rows x full DK=64), looping over S in 64-chunks.
// ---------------------------------------------------------------------------
__global__ void attend_kernel(const float* __restrict__ weights,
                              float* __restrict__ attended) {
    __shared__ float Ws[64][65];
    __shared__ float Vs[64][65];

    const int b  = blockIdx.y;
    const int m0 = blockIdx.x * 64;
    const float* wb = weights + (size_t)b * SEQ * SEQ;
    const float* Vb = g_V + (size_t)b * SEQ * DKK;

    const int tid = threadIdx.x;
    const int tx  = tid % 16;
    const int ty  = tid / 16;

    float acc[4][4] = {};
    for (int s0 = 0; s0 < SEQ; s0 += 64) {
        for (int i = tid; i < 64 * 64; i += 256) {
            const int r = i / 64, c = i % 64;
            Ws[r][c] = wb[(size_t)(m0 + r) * SEQ + s0 + c];
            Vs[r][c] = Vb[(size_t)(s0 + r) * DKK + c];
        }
        __syncthreads();
#pragma unroll
        for (int k = 0; k < 64; k++) {
            float wr[4], vr[4];
#pragma unroll
            for (int i = 0; i < 4; i++) wr[i] = Ws[ty * 4 + i][k];
#pragma unroll
            for (int j = 0; j < 4; j++) vr[j] = Vs[k][tx * 4 + j];
#pragma unroll
            for (int i = 0; i < 4; i++)
#pragma unroll
                for (int j = 0; j < 4; j++)
                    acc[i][j] += wr[i] * vr[j];
        }
        __syncthreads();
    }

#pragma unroll
    for (int i = 0; i < 4; i++) {
        const int row = m0 + ty * 4 + i;
        float4 v;
        v.x = acc[i][0];
        v.y = acc[i][1];
        v.z = acc[i][2];
        v.w = acc[i][3];
        *reinterpret_cast<float4*>(attended + ((size_t)b * SEQ + row) * DKK + tx * 4) = v;
    }
}

// ---------------------------------------------------------------------------
extern "C" void kernel_launch(void* const* d_in, const int* in_sizes, int n_in,
                              void* d_out, int out_size) {
    const float* in = (const float*)d_in[0];
    const float* Wq = (const float*)d_in[1];
    const float* Wk = (const float*)d_in[2];
    const float* Wv = (const float*)d_in[3];

    float* out      = (float*)d_out;
    float* attended = out;                               // [B,S,DK]
    float* weights  = out + (size_t)BATCH * SEQ * DKK;   // [B,S,S]

    // 1) QKV projection
    qkv_kernel<<<BATCH * SEQ, 192>>>(in, Wq, Wk, Wv);

    // 2) scores = scale * Q K^T  (written into weights region)
    dim3 g2(SEQ / 64, SEQ / 64, BATCH);
    scores_kernel<<<g2, 256>>>(weights);

    // 3) softmax in place
    softmax_kernel<<<BATCH * SEQ, 256>>>(weights);

    // 4) attended = weights @ V
    dim3 g4(SEQ / 64, BATCH);
    attend_kernel<<<g4, 256>>>(weights, attended);
}

// round 2
// speedup vs baseline: 2.4961x; 2.4961x over previous
#include <cuda_runtime.h>
#include <cuda_bf16.h>

#define BATCH 8
#define SEQ   2048
#define DIM   512
#define DKK   64
#define SP    40   // smem pitch in bf16 elems for 32-wide k tiles (bank-conflict-free)

// ------------------------- device scratch (module-load allocated) ----------
__device__ __nv_bfloat16 g_Qh[BATCH * SEQ * DKK];
__device__ __nv_bfloat16 g_Ql[BATCH * SEQ * DKK];
__device__ __nv_bfloat16 g_Kh[BATCH * SEQ * DKK];
__device__ __nv_bfloat16 g_Kl[BATCH * SEQ * DKK];
__device__ __nv_bfloat16 g_Vh[BATCH * SEQ * DKK];
__device__ __nv_bfloat16 g_Vl[BATCH * SEQ * DKK];
__device__ __nv_bfloat16 g_Wh[(size_t)BATCH * SEQ * SEQ];   // 64 MB
__device__ __nv_bfloat16 g_Wl[(size_t)BATCH * SEQ * SEQ];   // 64 MB
__device__ float         g_part[(size_t)8 * BATCH * SEQ * DKK]; // 32 MB split-S partials

// ------------------------- helpers -----------------------------------------
__device__ __forceinline__ void split2(float x0, float x1, unsigned &h, unsigned &l) {
    __nv_bfloat16 h0 = __float2bfloat16(x0);
    __nv_bfloat16 h1 = __float2bfloat16(x1);
    float r0 = x0 - __bfloat162float(h0);
    float r1 = x1 - __bfloat162float(h1);
    __nv_bfloat162 hv; hv.x = h0; hv.y = h1;
    __nv_bfloat162 lv; lv.x = __float2bfloat16(r0); lv.y = __float2bfloat16(r1);
    h = *reinterpret_cast<unsigned*>(&hv);
    l = *reinterpret_cast<unsigned*>(&lv);
}

__device__ __forceinline__ void mma16816(float* d, const unsigned* a, const unsigned* b) {
    asm volatile(
        "mma.sync.aligned.m16n8k16.row.col.f32.bf16.bf16.f32 "
        "{%0,%1,%2,%3},{%4,%5,%6,%7},{%8,%9},{%0,%1,%2,%3};"
        : "+f"(d[0]), "+f"(d[1]), "+f"(d[2]), "+f"(d[3])
        : "r"(a[0]), "r"(a[1]), "r"(a[2]), "r"(a[3]), "r"(b[0]), "r"(b[1]));
}

// ---------------------------------------------------------------------------
// Kernel 1: QKV projection via bf16-split MMA.
// C[16384,64] = in[16384,512] @ W[512,64] for which = {Q,K,V}.
// Block tile 128x64, 8 warps (4x2), warp tile 32x32. K chunks of 32.
// Epilogue writes split bf16 planes.
// ---------------------------------------------------------------------------
__global__ void __launch_bounds__(256) qkv_mma(const float* __restrict__ in,
                                               const float* __restrict__ Wq,
                                               const float* __restrict__ Wk,
                                               const float* __restrict__ Wv) {
    __shared__ __nv_bfloat16 sAh[128 * SP], sAl[128 * SP];
    __shared__ __nv_bfloat16 sBh[64 * SP],  sBl[64 * SP];

    const int m0    = blockIdx.x * 128;
    const int which = blockIdx.y;
    const float* W = (which == 0) ? Wq : (which == 1) ? Wk : Wv;
    __nv_bfloat16 *oh, *ol;
    if (which == 0)      { oh = g_Qh; ol = g_Ql; }
    else if (which == 1) { oh = g_Kh; ol = g_Kl; }
    else                 { oh = g_Vh; ol = g_Vl; }

    const int tid = threadIdx.x, lane = tid & 31, warp = tid >> 5;
    const int wr = warp >> 1, wc = warp & 1;      // warp: rows wr*32, cols wc*32
    const int gid = lane >> 2, tig = lane & 3;

    float acc[2][4][4] = {};

    for (int kc = 0; kc < 16; kc++) {
        const int k0 = kc * 32;
        // --- stage A: 128x32 fp32 -> split bf16 ---
#pragma unroll
        for (int j = 0; j < 4; j++) {
            int idx = tid + j * 256;               // 0..1023
            int r = idx >> 3, seg = idx & 7;       // seg: 4 floats
            float4 f = *(const float4*)&in[(size_t)(m0 + r) * DIM + k0 + seg * 4];
            unsigned h0, l0, h1, l1;
            split2(f.x, f.y, h0, l0);
            split2(f.z, f.w, h1, l1);
            *(unsigned*)&sAh[r * SP + seg * 4]     = h0;
            *(unsigned*)&sAh[r * SP + seg * 4 + 2] = h1;
            *(unsigned*)&sAl[r * SP + seg * 4]     = l0;
            *(unsigned*)&sAl[r * SP + seg * 4 + 2] = l1;
        }
        // --- stage B transposed: W[k0+kk][n] -> sB[n][kk], 32x64 ---
#pragma unroll
        for (int j = 0; j < 8; j++) {
            int idx = tid + j * 256;               // 0..2047
            int kk = idx >> 6, n = idx & 63;
            float v = W[(size_t)(k0 + kk) * DKK + n];
            __nv_bfloat16 h = __float2bfloat16(v);
            __nv_bfloat16 l = __float2bfloat16(v - __bfloat162float(h));
            sBh[n * SP + kk] = h;
            sBl[n * SP + kk] = l;
        }
        __syncthreads();

#pragma unroll
        for (int ks = 0; ks < 2; ks++) {
            const int kk = ks * 16;
            unsigned bh[4][2], bl[4][2];
#pragma unroll
            for (int nt = 0; nt < 4; nt++) {
                int n = wc * 32 + nt * 8 + gid;
                bh[nt][0] = *(unsigned*)&sBh[n * SP + kk + tig * 2];
                bh[nt][1] = *(unsigned*)&sBh[n * SP + kk + 8 + tig * 2];
                bl[nt][0] = *(unsigned*)&sBl[n * SP + kk + tig * 2];
                bl[nt][1] = *(unsigned*)&sBl[n * SP + kk + 8 + tig * 2];
            }
#pragma unroll
            for (int mt = 0; mt < 2; mt++) {
                int m = wr * 32 + mt * 16;
                unsigned ah[4], al[4];
                ah[0] = *(unsigned*)&sAh[(m + gid) * SP + kk + tig * 2];
                ah[1] = *(unsigned*)&sAh[(m + gid + 8) * SP + kk + tig * 2];
                ah[2] = *(unsigned*)&sAh[(m + gid) * SP + kk + 8 + tig * 2];
                ah[3] = *(unsigned*)&sAh[(m + gid + 8) * SP + kk + 8 + tig * 2];
                al[0] = *(unsigned*)&sAl[(m + gid) * SP + kk + tig * 2];
                al[1] = *(unsigned*)&sAl[(m + gid + 8) * SP + kk + tig * 2];
                al[2] = *(unsigned*)&sAl[(m + gid) * SP + kk + 8 + tig * 2];
                al[3] = *(unsigned*)&sAl[(m + gid + 8) * SP + kk + 8 + tig * 2];
#pragma unroll
                for (int nt = 0; nt < 4; nt++) {
                    mma16816(acc[mt][nt], ah, bh[nt]);
                    mma16816(acc[mt][nt], ah, bl[nt]);
                    mma16816(acc[mt][nt], al, bh[nt]);
                }
            }
        }
        __syncthreads();
    }

    // epilogue: split-write bf16 Q/K/V
#pragma unroll
    for (int mt = 0; mt < 2; mt++)
#pragma unroll
        for (int nt = 0; nt < 4; nt++) {
            int row = m0 + wr * 32 + mt * 16 + gid;
            int col = wc * 32 + nt * 8 + tig * 2;
            size_t o = (size_t)row * DKK + col;
            unsigned h, l;
            split2(acc[mt][nt][0], acc[mt][nt][1], h, l);
            *reinterpret_cast<unsigned*>(&oh[o]) = h;
            *reinterpret_cast<unsigned*>(&ol[o]) = l;
            split2(acc[mt][nt][2], acc[mt][nt][3], h, l);
            *reinterpret_cast<unsigned*>(&oh[o + (size_t)8 * DKK]) = h;
            *reinterpret_cast<unsigned*>(&ol[o + (size_t)8 * DKK]) = l;
        }
}

// ---------------------------------------------------------------------------
// Kernel 2: scores = 0.125 * Q @ K^T via bf16-split MMA.
// Block tile 128x128, 8 warps (2x4), warp tile 64x32. K = 64 in 2 chunks.
// ---------------------------------------------------------------------------
__global__ void __launch_bounds__(256) scores_mma(float* __restrict__ weights) {
    __shared__ __nv_bfloat16 sQh[128 * SP], sQl[128 * SP];
    __shared__ __nv_bfloat16 sKh[128 * SP], sKl[128 * SP];

    const int b  = blockIdx.z;
    const int m0 = blockIdx.y * 128;
    const int n0 = blockIdx.x * 128;
    const __nv_bfloat16* qh = g_Qh + (size_t)b * SEQ * DKK;
    const __nv_bfloat16* ql = g_Ql + (size_t)b * SEQ * DKK;
    const __nv_bfloat16* kh = g_Kh + (size_t)b * SEQ * DKK;
    const __nv_bfloat16* kl = g_Kl + (size_t)b * SEQ * DKK;

    const int tid = threadIdx.x, lane = tid & 31, warp = tid >> 5;
    const int wr = warp >> 2, wc = warp & 3;     // warp: rows wr*64, cols wc*32
    const int gid = lane >> 2, tig = lane & 3;

    float acc[4][4][4] = {};

    for (int kc = 0; kc < 2; kc++) {
        const int k0 = kc * 32;
#pragma unroll
        for (int j = 0; j < 2; j++) {
            int idx = tid + j * 256;               // 0..511
            int r = idx >> 2, seg = idx & 3;       // seg: 8 bf16 = uint4
            *(uint4*)&sQh[r * SP + seg * 8] = *(const uint4*)&qh[(size_t)(m0 + r) * DKK + k0 + seg * 8];
            *(uint4*)&sQl[r * SP + seg * 8] = *(const uint4*)&ql[(size_t)(m0 + r) * DKK + k0 + seg * 8];
            *(uint4*)&sKh[r * SP + seg * 8] = *(const uint4*)&kh[(size_t)(n0 + r) * DKK + k0 + seg * 8];
            *(uint4*)&sKl[r * SP + seg * 8] = *(const uint4*)&kl[(size_t)(n0 + r) * DKK + k0 + seg * 8];
        }
        __syncthreads();

#pragma unroll
        for (int ks = 0; ks < 2; ks++) {
            const int kk = ks * 16;
            unsigned bh[4][2], bl[4][2];
#pragma unroll
            for (int nt = 0; nt < 4; nt++) {
                int n = wc * 32 + nt * 8 + gid;
                bh[nt][0] = *(unsigned*)&sKh[n * SP + kk + tig * 2];
                bh[nt][1] = *(unsigned*)&sKh[n * SP + kk + 8 + tig * 2];
                bl[nt][0] = *(unsigned*)&sKl[n * SP + kk + tig * 2];
                bl[nt][1] = *(unsigned*)&sKl[n * SP + kk + 8 + tig * 2];
            }
#pragma unroll
            for (int mt = 0; mt < 4; mt++) {
                int m = wr * 64 + mt * 16;
                unsigned ah[4], al[4];
                ah[0] = *(unsigned*)&sQh[(m + gid) * SP + kk + tig * 2];
                ah[1] = *(unsigned*)&sQh[(m + gid + 8) * SP + kk + tig * 2];
                ah[2] = *(unsigned*)&sQh[(m + gid) * SP + kk + 8 + tig * 2];
                ah[3] = *(unsigned*)&sQh[(m + gid + 8) * SP + kk + 8 + tig * 2];
                al[0] = *(unsigned*)&sQl[(m + gid) * SP + kk + tig * 2];
                al[1] = *(unsigned*)&sQl[(m + gid + 8) * SP + kk + tig * 2];
                al[2] = *(unsigned*)&sQl[(m + gid) * SP + kk + 8 + tig * 2];
                al[3] = *(unsigned*)&sQl[(m + gid + 8) * SP + kk + 8 + tig * 2];
#pragma unroll
                for (int nt = 0; nt < 4; nt++) {
                    mma16816(acc[mt][nt], ah, bh[nt]);
                    mma16816(acc[mt][nt], ah, bl[nt]);
                    mma16816(acc[mt][nt], al, bh[nt]);
                }
            }
        }
        __syncthreads();
    }

    float* outb = weights + (size_t)b * SEQ * SEQ;
#pragma unroll
    for (int mt = 0; mt < 4; mt++)
#pragma unroll
        for (int nt = 0; nt < 4; nt++) {
            int row = m0 + wr * 64 + mt * 16 + gid;
            int col = n0 + wc * 32 + nt * 8 + tig * 2;
            float2 v0 = { acc[mt][nt][0] * 0.125f, acc[mt][nt][1] * 0.125f };
            float2 v1 = { acc[mt][nt][2] * 0.125f, acc[mt][nt][3] * 0.125f };
            *(float2*)&outb[(size_t)row * SEQ + col]       = v0;
            *(float2*)&outb[(size_t)(row + 8) * SEQ + col] = v1;
        }
}

// ---------------------------------------------------------------------------
// Kernel 3: row softmax (in place) + emit split bf16 weights for attend.
// ---------------------------------------------------------------------------
__global__ void __launch_bounds__(256) softmax_kernel(float* __restrict__ weights) {
    const int row = blockIdx.x;
    float* w = weights + (size_t)row * SEQ;
    const int tid = threadIdx.x, lane = tid & 31, warp = tid >> 5;

    float v[8];
    float mx = -3.4e38f;
#pragma unroll
    for (int i = 0; i < 8; i++) {
        v[i] = w[tid + i * 256];
        mx = fmaxf(mx, v[i]);
    }
#pragma unroll
    for (int o = 16; o > 0; o >>= 1)
        mx = fmaxf(mx, __shfl_xor_sync(0xffffffffu, mx, o));

    __shared__ float redmax[8], redsum[8];
    if (lane == 0) redmax[warp] = mx;
    __syncthreads();
    float bm = redmax[0];
#pragma unroll
    for (int i = 1; i < 8; i++) bm = fmaxf(bm, redmax[i]);

    float s = 0.f;
#pragma unroll
    for (int i = 0; i < 8; i++) { v[i] = __expf(v[i] - bm); s += v[i]; }
#pragma unroll
    for (int o = 16; o > 0; o >>= 1)
        s += __shfl_xor_sync(0xffffffffu, s, o);
    if (lane == 0) redsum[warp] = s;
    __syncthreads();
    float total = 0.f;
#pragma unroll
    for (int i = 0; i < 8; i++) total += redsum[i];
    const float inv = 1.0f / total;

    const size_t rb = (size_t)row * SEQ;
#pragma unroll
    for (int i = 0; i < 8; i++) {
        float val = v[i] * inv;
        int c = tid + i * 256;
        w[c] = val;
        __nv_bfloat16 h = __float2bfloat16(val);
        g_Wh[rb + c] = h;
        g_Wl[rb + c] = __float2bfloat16(val - __bfloat162float(h));
    }
}

// ---------------------------------------------------------------------------
// Kernel 4: attended partials = weights @ V via bf16-split MMA, split-S = 8.
// Block tile 128x64, 8 warps (4x2), warp tile 32x32. Each block: 256 of S.
// ---------------------------------------------------------------------------
__global__ void __launch_bounds__(256) attend_mma() {
    __shared__ __nv_bfloat16 sWh[128 * SP], sWl[128 * SP];
    __shared__ __nv_bfloat16 sVh[64 * SP],  sVl[64 * SP];

    const int m0    = blockIdx.x * 128;
    const int split = blockIdx.y;
    const int b     = blockIdx.z;
    const __nv_bfloat16* wh = g_Wh + (size_t)b * SEQ * SEQ;
    const __nv_bfloat16* wl = g_Wl + (size_t)b * SEQ * SEQ;
    const __nv_bfloat16* vh = g_Vh + (size_t)b * SEQ * DKK;
    const __nv_bfloat16* vl = g_Vl + (size_t)b * SEQ * DKK;

    const int tid = threadIdx.x, lane = tid & 31, warp = tid >> 5;
    const int wr = warp >> 1, wc = warp & 1;
    const int gid = lane >> 2, tig = lane & 3;

    float acc[2][4][4] = {};

    for (int kc = 0; kc < 8; kc++) {
        const int s0 = split * 256 + kc * 32;
        // stage weights tile 128x32
#pragma unroll
        for (int j = 0; j < 2; j++) {
            int idx = tid + j * 256;
            int r = idx >> 2, seg = idx & 3;
            *(uint4*)&sWh[r * SP + seg * 8] = *(const uint4*)&wh[(size_t)(m0 + r) * SEQ + s0 + seg * 8];
            *(uint4*)&sWl[r * SP + seg * 8] = *(const uint4*)&wl[(size_t)(m0 + r) * SEQ + s0 + seg * 8];
        }
        // stage V transposed: sV[n][kk] = V[s0+kk][n]
#pragma unroll
        for (int j = 0; j < 8; j++) {
            int idx = tid + j * 256;               // 0..2047
            int kk = idx >> 6, n = idx & 63;
            sVh[n * SP + kk] = vh[(size_t)(s0 + kk) * DKK + n];
            sVl[n * SP + kk] = vl[(size_t)(s0 + kk) * DKK + n];
        }
        __syncthreads();

#pragma unroll
        for (int ks = 0; ks < 2; ks++) {
            const int kk = ks * 16;
            unsigned bh[4][2], bl[4][2];
#pragma unroll
            for (int nt = 0; nt < 4; nt++) {
                int n = wc * 32 + nt * 8 + gid;
                bh[nt][0] = *(unsigned*)&sVh[n * SP + kk + tig * 2];
                bh[nt][1] = *(unsigned*)&sVh[n * SP + kk + 8 + tig * 2];
                bl[nt][0] = *(unsigned*)&sVl[n * SP + kk + tig * 2];
                bl[nt][1] = *(unsigned*)&sVl[n * SP + kk + 8 + tig * 2];
            }
#pragma unroll
            for (int mt = 0; mt < 2; mt++) {
                int m = wr * 32 + mt * 16;
                unsigned ah[4], al[4];
                ah[0] = *(unsigned*)&sWh[(m + gid) * SP + kk + tig * 2];
                ah[1] = *(unsigned*)&sWh[(m + gid + 8) * SP + kk + tig * 2];
                ah[2] = *(unsigned*)&sWh[(m + gid) * SP + kk + 8 + tig * 2];
                ah[3] = *(unsigned*)&sWh[(m + gid + 8) * SP + kk + 8 + tig * 2];
                al[0] = *(unsigned*)&sWl[(m + gid) * SP + kk + tig * 2];
                al[1] = *(unsigned*)&sWl[(m + gid + 8) * SP + kk + tig * 2];
                al[2] = *(unsigned*)&sWl[(m + gid) * SP + kk + 8 + tig * 2];
                al[3] = *(unsigned*)&sWl[(m + gid + 8) * SP + kk + 8 + tig * 2];
#pragma unroll
                for (int nt = 0; nt < 4; nt++) {
                    mma16816(acc[mt][nt], ah, bh[nt]);
                    mma16816(acc[mt][nt], ah, bl[nt]);
                    mma16816(acc[mt][nt], al, bh[nt]);
                }
            }
        }
        __syncthreads();
    }

    float* part = g_part + ((size_t)(split * BATCH + b)) * SEQ * DKK;
#pragma unroll
    for (int mt = 0; mt < 2; mt++)
#pragma unroll
        for (int nt = 0; nt < 4; nt++) {
            int row = m0 + wr * 32 + mt * 16 + gid;
            int col = wc * 32 + nt * 8 + tig * 2;
            float2 v0 = { acc[mt][nt][0], acc[mt][nt][1] };
            float2 v1 = { acc[mt][nt][2], acc[mt][nt][3] };
            *(float2*)&part[(size_t)row * DKK + col]       = v0;
            *(float2*)&part[(size_t)(row + 8) * DKK + col] = v1;
        }
}

// ---------------------------------------------------------------------------
// Kernel 5: deterministic split-S reduction.
// ---------------------------------------------------------------------------
__global__ void __launch_bounds__(256) reduce_part(float* __restrict__ attended) {
    const size_t P = (size_t)BATCH * SEQ * DKK;
    size_t i = (size_t)blockIdx.x * 256 + threadIdx.x;
    float s = 0.f;
#pragma unroll
    for (int k = 0; k < 8; k++) s += g_part[(size_t)k * P + i];
    attended[i] = s;
}

// ---------------------------------------------------------------------------
extern "C" void kernel_launch(void* const* d_in, const int* in_sizes, int n_in,
                              void* d_out, int out_size) {
    const float* in = (const float*)d_in[0];
    const float* Wq = (const float*)d_in[1];
    const float* Wk = (const float*)d_in[2];
    const float* Wv = (const float*)d_in[3];

    float* out      = (float*)d_out;
    float* attended = out;                               // [B,S,DK]
    float* weights  = out + (size_t)BATCH * SEQ * DKK;   // [B,S,S]

    // 1) QKV projection (bf16-split MMA), writes split bf16 Q/K/V
    dim3 g1(SEQ * BATCH / 128, 3);
    qkv_mma<<<g1, 256>>>(in, Wq, Wk, Wv);

    // 2) scores = 0.125 * Q K^T
    dim3 g2(SEQ / 128, SEQ / 128, BATCH);
    scores_mma<<<g2, 256>>>(weights);

    // 3) softmax in place + emit split bf16 weights
    softmax_kernel<<<BATCH * SEQ, 256>>>(weights);

    // 4) attended partials (split-S = 8)
    dim3 g4(SEQ / 128, 8, BATCH);
    attend_mma<<<g4, 256>>>();

    // 5) reduce partials
    reduce_part<<<(BATCH * SEQ * DKK) / 256, 256>>>(attended);
}